// round 17
// baseline (speedup 1.0000x reference)
#include <cuda_runtime.h>
#include <cuda_bf16.h>
#include <math.h>
#include <stdint.h>

#define NN 50000
#define EE 800000
#define FF 128
#define HH 8
#define LL 4

#define SCAN_B 256
#define SCAN_NB ((NN + SCAN_B - 1) / SCAN_B)   // 196
#define MTILES ((NN + 127) / 128)              // 391

// smem tile geometry: 128 rows x 64 bf16 cols (BK=64), padded to 72 (144B rows)
#define SJ2 72
#define WS2 (SJ2 / 2)                          // 36 words per row
#define TILE2_BYTES (128 * SJ2 * 2)            // 18432
#define SMEM2_TOTAL (4 * TILE2_BYTES)          // 73728

// ---------------- scratch (static device allocations; no cudaMalloc) ----------------
__device__ float g_Q[NN * FF];
__device__ float g_K[NN * FF];
__device__ float g_V[NN * FF];
__device__ float g_S[NN * FF];
__device__ float g_stageA[EE * HH];                // CSR-ordered raw alphas, ping
__device__ float g_stageB[EE * HH];                // pong
__device__ float g_mA[NN * HH], g_invA[NN * HH];   // per-node/head softmax stats, ping
__device__ float g_mB[NN * HH], g_invB[NN * HH];   // pong
__device__ float g_alpha_stage[EE * HH];           // fallback final sink if out buffer lacks room
__device__ __nv_bfloat16 g_X0[NN * FF];            // hi split of layer input
__device__ __nv_bfloat16 g_X1[NN * FF];            // lo split
__device__ __nv_bfloat16 g_B0[LL * 4 * FF * FF];   // W^T hi split, [l][which][n][k]
__device__ __nv_bfloat16 g_B1[LL * 4 * FF * FF];   // W^T lo split
__device__ int g_deg[NN];
__device__ int g_rowptr[NN + 1];
__device__ int g_cursor[NN];
__device__ int g_eidx[EE];
__device__ int g_srcs[EE];
__device__ int g_is64;
__device__ int g_blocksum[SCAN_NB];

// ---------------- dtype detection ----------------
__global__ void detect_kernel(const int* __restrict__ ei32) {
    int zeros = 0;
    for (int i = 0; i < 64; i++)
        if (ei32[2 * i + 1] == 0) zeros++;
    g_is64 = (zeros >= 48) ? 1 : 0;
}

__device__ __forceinline__ int load_idx(const void* eiv, long long pos) {
    if (g_is64) return (int)((const long long*)eiv)[pos];
    return ((const int*)eiv)[pos];
}

// ---------------- CSR construction ----------------
__global__ void zero_deg_kernel() {
    int i = blockIdx.x * blockDim.x + threadIdx.x;
    if (i < NN) g_deg[i] = 0;
}

__global__ void hist_kernel(const void* __restrict__ eiv) {
    int e = blockIdx.x * blockDim.x + threadIdx.x;
    if (e < EE) {
        int d = load_idx(eiv, (long long)EE + e);
        if (d >= 0 && d < NN) atomicAdd(&g_deg[d], 1);
    }
}

__global__ void __launch_bounds__(SCAN_B) reduce_kernel() {
    int tid = threadIdx.x, lane = tid & 31, wid = tid >> 5;
    int i = blockIdx.x * SCAN_B + tid;
    int v = (i < NN) ? g_deg[i] : 0;
#pragma unroll
    for (int o = 16; o > 0; o >>= 1) v += __shfl_down_sync(0xffffffffu, v, o);
    __shared__ int ws[8];
    if (lane == 0) ws[wid] = v;
    __syncthreads();
    if (tid == 0) {
        int s = 0;
#pragma unroll
        for (int w = 0; w < 8; w++) s += ws[w];
        g_blocksum[blockIdx.x] = s;
    }
}

__device__ __forceinline__ int block_incl_scan(int v, int tid) {
    int lane = tid & 31, wid = tid >> 5;
    int x = v;
#pragma unroll
    for (int o = 1; o < 32; o <<= 1) {
        int t = __shfl_up_sync(0xffffffffu, x, o);
        if (lane >= o) x += t;
    }
    __shared__ int wsum[8];
    if (lane == 31) wsum[wid] = x;
    __syncthreads();
    if (wid == 0) {
        int y = (lane < 8) ? wsum[lane] : 0;
#pragma unroll
        for (int o = 1; o < 8; o <<= 1) {
            int t = __shfl_up_sync(0xffffffffu, y, o);
            if (lane >= o) y += t;
        }
        if (lane < 8) wsum[lane] = y;
    }
    __syncthreads();
    return x + ((wid > 0) ? wsum[wid - 1] : 0);
}

__global__ void __launch_bounds__(SCAN_B) scanpart_kernel() {
    int tid = threadIdx.x;
    int v = (tid < SCAN_NB) ? g_blocksum[tid] : 0;
    int incl = block_incl_scan(v, tid);
    if (tid < SCAN_NB) g_blocksum[tid] = incl - v;
}

__global__ void __launch_bounds__(SCAN_B) scanfinal_kernel() {
    int tid = threadIdx.x;
    int i = blockIdx.x * SCAN_B + tid;
    int v = (i < NN) ? g_deg[i] : 0;
    int incl = block_incl_scan(v, tid);
    int off = g_blocksum[blockIdx.x];
    if (i < NN) {
        int e = off + incl - v;
        g_rowptr[i] = e;
        g_cursor[i] = e;
    }
    if (i == NN - 1) g_rowptr[NN] = off + incl;
}

__global__ void scatter_kernel(const void* __restrict__ eiv) {
    int e = blockIdx.x * blockDim.x + threadIdx.x;
    if (e < EE) {
        int s = load_idx(eiv, e);
        int d = load_idx(eiv, (long long)EE + e);
        if (d >= 0 && d < NN && s >= 0 && s < NN) {
            int p = atomicAdd(&g_cursor[d], 1);
            if (p >= 0 && p < EE) {
                g_eidx[p] = e;
                g_srcs[p] = s;
            }
        }
    }
}

// ---------------- split helpers (fp32 -> hi/lo bf16) ----------------
__device__ __forceinline__ void split_bf16(float v, __nv_bfloat16& hi, __nv_bfloat16& lo) {
    hi = __float2bfloat16_rn(v);
    lo = __float2bfloat16_rn(v - __bfloat162float(hi));
}

__global__ void __launch_bounds__(256) splitx_kernel(const float* __restrict__ X) {
    int i = blockIdx.x * blockDim.x + threadIdx.x;   // float4 index
    if (i < NN * FF / 4) {
        float4 v = ((const float4*)X)[i];
        __nv_bfloat16 h0, l0, h1, l1, h2, l2, h3, l3;
        split_bf16(v.x, h0, l0); split_bf16(v.y, h1, l1);
        split_bf16(v.z, h2, l2); split_bf16(v.w, h3, l3);
        ((__nv_bfloat162*)g_X0)[2 * i]     = __nv_bfloat162(h0, h1);
        ((__nv_bfloat162*)g_X0)[2 * i + 1] = __nv_bfloat162(h2, h3);
        ((__nv_bfloat162*)g_X1)[2 * i]     = __nv_bfloat162(l0, l1);
        ((__nv_bfloat162*)g_X1)[2 * i + 1] = __nv_bfloat162(l2, l3);
    }
}

__global__ void __launch_bounds__(256) splitw_all_kernel(
    const float* __restrict__ Wq, const float* __restrict__ Wk,
    const float* __restrict__ Wv, const float* __restrict__ Ws)
{
    int idx = blockIdx.x * blockDim.x + threadIdx.x;   // l*65536 + which*16384 + k*128 + n
    if (idx < LL * 4 * FF * FF) {
        int l = idx >> 16;
        int which = (idx >> 14) & 3;
        int r = idx & 16383;
        int k = r >> 7, n = r & 127;
        const float* W = (which == 0) ? Wq : ((which == 1) ? Wk : ((which == 2) ? Wv : Ws));
        float v = W[(size_t)l * FF * FF + r];
        __nv_bfloat16 hi, lo;
        split_bf16(v, hi, lo);
        size_t base = ((size_t)(l * 4 + which)) << 14;
        g_B0[base + n * FF + k] = hi;
        g_B1[base + n * FF + k] = lo;
    }
}

// ---------------- bf16 mma.sync GEMM: O = X @ W + b via 3-product split ----------------
__device__ __forceinline__ void mma_bf16(float* c, const uint32_t* a, const uint32_t* b) {
    asm volatile(
        "mma.sync.aligned.m16n8k16.row.col.f32.bf16.bf16.f32 "
        "{%0,%1,%2,%3}, {%4,%5,%6,%7}, {%8,%9}, {%0,%1,%2,%3};"
        : "+f"(c[0]), "+f"(c[1]), "+f"(c[2]), "+f"(c[3])
        : "r"(a[0]), "r"(a[1]), "r"(a[2]), "r"(a[3]), "r"(b[0]), "r"(b[1]));
}

// grid (MTILES, 4), 256 threads, BK=64 x 2 steps, 73.7 KB smem -> 2 CTAs/SM.
__global__ void __launch_bounds__(256, 2) gemm_mma_kernel(
    int l,
    const float* __restrict__ b0, const float* __restrict__ b1,
    const float* __restrict__ b2, const float* __restrict__ b3)
{
    extern __shared__ char smem[];
    uint32_t* A0w = (uint32_t*)smem;
    uint32_t* A1w = (uint32_t*)(smem + TILE2_BYTES);
    uint32_t* B0w = (uint32_t*)(smem + 2 * TILE2_BYTES);
    uint32_t* B1w = (uint32_t*)(smem + 3 * TILE2_BYTES);

    int tid = threadIdx.x;
    int wid = tid >> 5, lane = tid & 31;
    int which = blockIdx.y;
    int row0 = blockIdx.x * 128;
    const float* bias = (which == 0) ? b0 : ((which == 1) ? b1 : ((which == 2) ? b2 : b3));
    float* O = (which == 0) ? g_Q : ((which == 1) ? g_K : ((which == 2) ? g_V : g_S));

    int wm = (wid >> 2) * 64;
    int wn = (wid & 3) * 32;
    int g = lane >> 2, tg = lane & 3;

    float c[4][4][4];
#pragma unroll
    for (int mt = 0; mt < 4; mt++)
#pragma unroll
        for (int nt = 0; nt < 4; nt++)
#pragma unroll
            for (int r = 0; r < 4; r++) c[mt][nt][r] = 0.f;

    int arow[4], brow[4];
#pragma unroll
    for (int mt = 0; mt < 4; mt++) arow[mt] = (wm + mt * 16 + g) * WS2;
#pragma unroll
    for (int nt = 0; nt < 4; nt++) brow[nt] = (wn + nt * 8 + g) * WS2;

    const uint4* xa0 = (const uint4*)g_X0;
    const uint4* xa1 = (const uint4*)g_X1;
    size_t wbase = ((size_t)(l * 4 + which)) << 14;
    const uint4* wb0 = (const uint4*)(g_B0 + wbase);
    const uint4* wb1 = (const uint4*)(g_B1 + wbase);
    const uint4 z4 = make_uint4(0u, 0u, 0u, 0u);

#pragma unroll
    for (int kc = 0; kc < 2; kc++) {
#pragma unroll
        for (int it = 0; it < 4; it++) {
            int i = tid + it * 256;          // 0..1023
            int row = i >> 3, c8 = i & 7;    // 8 uint4 chunks per row
            int so = row * (WS2 / 4) + c8;   // uint4 index (9 per padded row)
            bool ok = (row0 + row) < NN;
            size_t gi = (size_t)(row0 + row) * 16 + kc * 8 + c8;
            ((uint4*)A0w)[so] = ok ? xa0[gi] : z4;
            ((uint4*)A1w)[so] = ok ? xa1[gi] : z4;
            size_t bi = (size_t)row * 16 + kc * 8 + c8;
            ((uint4*)B0w)[so] = wb0[bi];
            ((uint4*)B1w)[so] = wb1[bi];
        }
        __syncthreads();

#pragma unroll
        for (int ks = 0; ks < 4; ks++) {
            int kw = ks * 8 + tg;
            uint32_t ah[4][4], bh[4][2], al[4][4], bl[4][2];
#pragma unroll
            for (int mt = 0; mt < 4; mt++) {
                ah[mt][0] = A0w[arow[mt] + kw];
                ah[mt][1] = A0w[arow[mt] + 8 * WS2 + kw];
                ah[mt][2] = A0w[arow[mt] + kw + 4];
                ah[mt][3] = A0w[arow[mt] + 8 * WS2 + kw + 4];
            }
#pragma unroll
            for (int nt = 0; nt < 4; nt++) {
                bh[nt][0] = B0w[brow[nt] + kw];
                bh[nt][1] = B0w[brow[nt] + kw + 4];
            }
#pragma unroll
            for (int mt = 0; mt < 4; mt++)
#pragma unroll
                for (int nt = 0; nt < 4; nt++) mma_bf16(c[mt][nt], ah[mt], bh[nt]);

#pragma unroll
            for (int nt = 0; nt < 4; nt++) {
                bl[nt][0] = B1w[brow[nt] + kw];
                bl[nt][1] = B1w[brow[nt] + kw + 4];
            }
#pragma unroll
            for (int mt = 0; mt < 4; mt++)
#pragma unroll
                for (int nt = 0; nt < 4; nt++) mma_bf16(c[mt][nt], ah[mt], bl[nt]);

#pragma unroll
            for (int mt = 0; mt < 4; mt++) {
                al[mt][0] = A1w[arow[mt] + kw];
                al[mt][1] = A1w[arow[mt] + 8 * WS2 + kw];
                al[mt][2] = A1w[arow[mt] + kw + 4];
                al[mt][3] = A1w[arow[mt] + 8 * WS2 + kw + 4];
            }
#pragma unroll
            for (int mt = 0; mt < 4; mt++)
#pragma unroll
                for (int nt = 0; nt < 4; nt++) mma_bf16(c[mt][nt], al[mt], bh[nt]);
        }
        __syncthreads();
    }

#pragma unroll
    for (int mt = 0; mt < 4; mt++) {
#pragma unroll
        for (int nt = 0; nt < 4; nt++) {
            int col = wn + nt * 8 + tg * 2;
            float bx = bias[col], by = bias[col + 1];
            int row = row0 + wm + mt * 16 + g;
            if (row < NN) {
                float2* p = (float2*)(O + (size_t)row * FF + col);
                *p = make_float2(c[mt][nt][0] + bx, c[mt][nt][1] + by);
            }
            if (row + 8 < NN) {
                float2* p = (float2*)(O + (size_t)(row + 8) * FF + col);
                *p = make_float2(c[mt][nt][2] + bx, c[mt][nt][3] + by);
            }
        }
    }
}

// ---------------- edge phase v5: passes 1-2 only; alpha finalize deferred ----------------
__device__ __forceinline__ float dot4(float4 a, float4 b) {
    return a.x * b.x + a.y * b.y + a.z * b.z + a.w * b.w;
}

__global__ void __launch_bounds__(256) edge_kernel(
    int final_layer, float* __restrict__ out_h,
    float* __restrict__ stage, float* __restrict__ mArr, float* __restrict__ invArr)
{
    int gw = (blockIdx.x * blockDim.x + threadIdx.x) >> 5;
    int lane = threadIdx.x & 31;
    if (gw >= NN) return;
    int n = gw;
    int beg = g_rowptr[n];
    int end = g_rowptr[n + 1];

    float4 q4 = ((const float4*)(g_Q + (size_t)n * FF))[lane];
    int h = lane >> 2;

    // ---- pass 1: raw alphas to stage + max (2 edges in flight) ----
    float m = -3.0e38f;
    int p = beg;
    for (; p + 2 <= end; p += 2) {
        int s0 = g_srcs[p], s1 = g_srcs[p + 1];
        float4 k0 = ((const float4*)(g_K + (size_t)s0 * FF))[lane];
        float4 k1 = ((const float4*)(g_K + (size_t)s1 * FF))[lane];
        float d0 = dot4(q4, k0);
        float d1 = dot4(q4, k1);
        d0 += __shfl_xor_sync(0xffffffffu, d0, 1);
        d1 += __shfl_xor_sync(0xffffffffu, d1, 1);
        d0 += __shfl_xor_sync(0xffffffffu, d0, 2);
        d1 += __shfl_xor_sync(0xffffffffu, d1, 2);
        float a0 = d0 * 0.25f, a1 = d1 * 0.25f;
        if ((lane & 3) == 0) {
            stage[(size_t)p * HH + h] = a0;
            stage[(size_t)(p + 1) * HH + h] = a1;
        }
        m = fmaxf(m, fmaxf(a0, a1));
    }
    if (p < end) {
        int s = g_srcs[p];
        float4 k4 = ((const float4*)(g_K + (size_t)s * FF))[lane];
        float d = dot4(q4, k4);
        d += __shfl_xor_sync(0xffffffffu, d, 1);
        d += __shfl_xor_sync(0xffffffffu, d, 2);
        float alpha = d * 0.25f;
        if ((lane & 3) == 0) stage[(size_t)p * HH + h] = alpha;
        m = fmaxf(m, alpha);
    }
    __syncwarp();

    // ---- pass 2: denom + weighted V (2 edges in flight) ----
    float denom = 0.f;
    float4 acc = make_float4(0.f, 0.f, 0.f, 0.f);
    p = beg;
    for (; p + 2 <= end; p += 2) {
        int s0 = g_srcs[p], s1 = g_srcs[p + 1];
        float a0 = stage[(size_t)p * HH + h];
        float a1 = stage[(size_t)(p + 1) * HH + h];
        float4 v0 = ((const float4*)(g_V + (size_t)s0 * FF))[lane];
        float4 v1 = ((const float4*)(g_V + (size_t)s1 * FF))[lane];
        float pe0 = __expf(a0 - m);
        float pe1 = __expf(a1 - m);
        denom += pe0 + pe1;
        acc.x += pe0 * v0.x + pe1 * v1.x;
        acc.y += pe0 * v0.y + pe1 * v1.y;
        acc.z += pe0 * v0.z + pe1 * v1.z;
        acc.w += pe0 * v0.w + pe1 * v1.w;
    }
    if (p < end) {
        int s = g_srcs[p];
        float a = stage[(size_t)p * HH + h];
        float pe = __expf(a - m);
        float4 v4 = ((const float4*)(g_V + (size_t)s * FF))[lane];
        denom += pe;
        acc.x += pe * v4.x;
        acc.y += pe * v4.y;
        acc.z += pe * v4.z;
        acc.w += pe * v4.w;
    }

    float inv = (end > beg && denom > 0.f) ? 1.f / denom : 0.f;

    // softmax stats for deferred finalize
    if ((lane & 3) == 0) {
        mArr[(size_t)n * HH + h] = m;
        invArr[(size_t)n * HH + h] = inv;
    }

    // ---- epilogue: node output ----
    float4 s4 = ((const float4*)(g_S + (size_t)n * FF))[lane];
    float4 o;
    o.x = acc.x * inv + s4.x;
    o.y = acc.y * inv + s4.y;
    o.z = acc.z * inv + s4.z;
    o.w = acc.w * inv + s4.w;
    if (!final_layer) {
        o.x = 0.5f * o.x * (1.f + erff(o.x * 0.70710678118654752f));
        o.y = 0.5f * o.y * (1.f + erff(o.y * 0.70710678118654752f));
        o.z = 0.5f * o.z * (1.f + erff(o.z * 0.70710678118654752f));
        o.w = 0.5f * o.w * (1.f + erff(o.w * 0.70710678118654752f));
        __nv_bfloat16 h0, l0, h1, l1, h2c, l2, h3, l3;
        split_bf16(o.x, h0, l0); split_bf16(o.y, h1, l1);
        split_bf16(o.z, h2c, l2); split_bf16(o.w, h3, l3);
        __nv_bfloat162* p0 = (__nv_bfloat162*)(g_X0 + (size_t)n * FF);
        __nv_bfloat162* p1 = (__nv_bfloat162*)(g_X1 + (size_t)n * FF);
        p0[lane * 2]     = __nv_bfloat162(h0, h1);
        p0[lane * 2 + 1] = __nv_bfloat162(h2c, h3);
        p1[lane * 2]     = __nv_bfloat162(l0, l1);
        p1[lane * 2 + 1] = __nv_bfloat162(l2, l3);
    } else {
        __stcs((float4*)(out_h + (size_t)n * FF) + lane, o);
    }
}

// ---------------- deferred alpha finalize: overlapped on side stream ----------------
__global__ void __launch_bounds__(256) finalize_kernel(
    const float* __restrict__ stage, const float* __restrict__ mArr,
    const float* __restrict__ invArr, float* __restrict__ alpha_out)
{
    int gw = (blockIdx.x * blockDim.x + threadIdx.x) >> 5;
    int lane = threadIdx.x & 31;
    if (gw >= NN) return;
    int beg = g_rowptr[gw];
    int end = g_rowptr[gw + 1];
    int h2 = lane & 7;
    float mh = mArr[(size_t)gw * HH + h2];
    float invh = invArr[(size_t)gw * HH + h2];
    for (int p0i = beg; p0i < end; p0i += 4) {
        int pp = p0i + (lane >> 3);
        if (pp < end) {
            float a = stage[(size_t)p0i * HH + lane];   // coalesced 128B per warp
            __stcs(&alpha_out[(size_t)g_eidx[pp] * HH + h2], __expf(a - mh) * invh);
        }
    }
}

static float* sym_ptr(const void* sym) {
    void* p = nullptr;
    cudaGetSymbolAddress(&p, sym);
    return (float*)p;
}

// ---------------- launch ----------------
extern "C" void kernel_launch(void* const* d_in, const int* in_sizes, int n_in,
                              void* d_out, int out_size)
{
    const float* x = (const float*)d_in[0];
    const void* ei = (const void*)d_in[1];
    const float* Wq = (const float*)d_in[2];
    const float* bq = (const float*)d_in[3];
    const float* Wk = (const float*)d_in[4];
    const float* bk = (const float*)d_in[5];
    const float* Wv = (const float*)d_in[6];
    const float* bv = (const float*)d_in[7];
    const float* Ws = (const float*)d_in[8];
    const float* bs = (const float*)d_in[9];
    float* out = (float*)d_out;

    cudaFuncSetAttribute(gemm_mma_kernel, cudaFuncAttributeMaxDynamicSharedMemorySize, SMEM2_TOTAL);

    // static side stream + events (created once on the first, non-captured call)
    static cudaStream_t s_side = nullptr;
    static cudaEvent_t s_fork = nullptr, s_join = nullptr;
    static cudaEvent_t s_edge[LL] = {};
    static cudaEvent_t s_fin[LL] = {};
    if (s_side == nullptr) {
        cudaStreamCreateWithFlags(&s_side, cudaStreamNonBlocking);
        cudaEventCreateWithFlags(&s_fork, cudaEventDisableTiming);
        cudaEventCreateWithFlags(&s_join, cudaEventDisableTiming);
        for (int l = 0; l < LL; l++) {
            cudaEventCreateWithFlags(&s_edge[l], cudaEventDisableTiming);
            cudaEventCreateWithFlags(&s_fin[l], cudaEventDisableTiming);
        }
    }

    const long long full_elems = (long long)NN * FF + (long long)LL * EE * HH;
    bool alphas_in_out = ((long long)out_size >= full_elems);
    float* fallback = alphas_in_out ? nullptr : sym_ptr(g_alpha_stage);

    float* stageP[2] = {sym_ptr(g_stageA), sym_ptr(g_stageB)};
    float* mP[2]     = {sym_ptr(g_mA),     sym_ptr(g_mB)};
    float* invP[2]   = {sym_ptr(g_invA),   sym_ptr(g_invB)};

    // ---- fork: CSR build on side stream; splits + gemm0 on main stream ----
    cudaEventRecord(s_fork, 0);
    cudaStreamWaitEvent(s_side, s_fork, 0);

    detect_kernel<<<1, 1, 0, s_side>>>((const int*)ei);
    zero_deg_kernel<<<(NN + 255) / 256, 256, 0, s_side>>>();
    hist_kernel<<<(EE + 255) / 256, 256, 0, s_side>>>(ei);
    reduce_kernel<<<SCAN_NB, SCAN_B, 0, s_side>>>();
    scanpart_kernel<<<1, SCAN_B, 0, s_side>>>();
    scanfinal_kernel<<<SCAN_NB, SCAN_B, 0, s_side>>>();
    scatter_kernel<<<(EE + 255) / 256, 256, 0, s_side>>>(ei);
    cudaEventRecord(s_join, s_side);

    splitw_all_kernel<<<(LL * 4 * FF * FF + 255) / 256, 256>>>(Wq, Wk, Wv, Ws);
    splitx_kernel<<<(NN * FF / 4 + 255) / 256, 256>>>(x);

    dim3 ggrid(MTILES, 4);
    int eblocks = (NN * 32 + 255) / 256;

    for (int l = 0; l < LL; l++) {
        int pb = l & 1;   // ping-pong buffer index
        size_t bofs = (size_t)l * FF;
        gemm_mma_kernel<<<ggrid, 256, SMEM2_TOTAL>>>(l, bq + bofs, bk + bofs, bv + bofs, bs + bofs);
        if (l == 0) cudaStreamWaitEvent(0, s_join, 0);       // CSR ready before first edge pass
        if (l >= 2) cudaStreamWaitEvent(0, s_fin[l - 2], 0); // buffer pb free again
        edge_kernel<<<eblocks, 256>>>((l == LL - 1) ? 1 : 0, out,
                                      stageP[pb], mP[pb], invP[pb]);
        cudaEventRecord(s_edge[l], 0);

        // deferred alpha finalize on side stream (overlaps next layer's GEMM+edge)
        float* alpha_out = alphas_in_out
            ? (out + (size_t)NN * FF + (size_t)l * EE * HH)
            : fallback;
        cudaStreamWaitEvent(s_side, s_edge[l], 0);
        finalize_kernel<<<eblocks, 256, 0, s_side>>>(stageP[pb], mP[pb], invP[pb], alpha_out);
        cudaEventRecord(s_fin[l], s_side);
    }

    // join: all finalizes must complete before the graph's end
    cudaStreamWaitEvent(0, s_fin[LL - 1], 0);
}